// round 14
// baseline (speedup 1.0000x reference)
#include <cuda_runtime.h>

// 2-layer LSTM (B=2048, T=1000, I=13, H=32) + Linear(32)->ReLU->Linear(3).
// 148 blocks x 512 threads (occupancy play). Block = two independent 7-batch
// halves of 256 threads. Half = L0 group (128 thr) + L1 group (128 thr),
// pipelined one step apart over double-buffered h0 (parity-split barriers,
// R10 topology). NEW vs R10: K-SPLIT — each group thread owns rows
// (rl, rl+64) but only HALF the k-range (kh), halving weight registers
// (fits 512 thr/block -> 4 warps/SMSP instead of 2). GEMMs write k-partial
// gates; EW (2 cells/thread over 128 threads) sums the two partials while
// reading. FMA floor unchanged; exposed latency per step halves.

#define BB    2048
#define TT    1000
#define II    13
#define HH    32
#define NC    3
#define NBH   7            // batches per half
#define BPB   14
#define GRIDN 148
#define GSTR  9            // gate smem row stride (coprime with 32 banks)
#define KH1   (128 * GSTR) // kh=1 partial offset

typedef unsigned long long ull;

struct alignas(16) Smem {
    float xs[2][2][NBH][16];         // [half][parity][b][k], k padded 13->16
    float h0[2][2][NBH][HH];         // [half][slot][b][k]
    float h1[2][NBH][HH];            // [half][b][k]
    float pg[2][2][2][128 * GSTR];   // [half][grp][kh][row*GSTR + b]
};

__device__ __forceinline__ ull ffma2(ull a, ull b, ull c) {
    ull d;
    asm("fma.rn.f32x2 %0, %1, %2, %3;" : "=l"(d) : "l"(a), "l"(b), "l"(c));
    return d;
}
__device__ __forceinline__ ull packf2(float lo, float hi) {
    ull r;
    asm("mov.b64 %0, {%1, %2};" : "=l"(r) : "f"(lo), "f"(hi));
    return r;
}
__device__ __forceinline__ float hadd2(ull a) {
    float lo, hi;
    asm("mov.b64 {%0, %1}, %2;" : "=f"(lo), "=f"(hi) : "l"(a));
    return lo + hi;
}
__device__ __forceinline__ ull d2l(double d) { return __double_as_longlong(d); }

__device__ __forceinline__ float tanhap(float v) {
    float y;
    asm("tanh.approx.f32 %0, %1;" : "=f"(y) : "f"(v));
    return y;
}
__device__ __forceinline__ float sigf(float v) {
    return fmaf(tanhap(0.5f * v), 0.5f, 0.5f);
}

// acc[i][b] += sum over NC4 float4-chunks of vb: v-pairs * w{i}-pairs (f32x2)
template <int NC4, int BSTR>
__device__ __forceinline__ void gemm2(ull (&acc)[2][NBH], const float* __restrict__ vb,
                                      const ull (&w0)[8], const ull (&w1)[8]) {
#pragma unroll
    for (int c = 0; c < NC4; c++) {
#pragma unroll
        for (int b = 0; b < NBH; b++) {
            double2 v = *reinterpret_cast<const double2*>(vb + b * BSTR + c * 4);
            ull vx = d2l(v.x), vy = d2l(v.y);
            acc[0][b] = ffma2(vx, w0[2 * c],     acc[0][b]);
            acc[0][b] = ffma2(vy, w0[2 * c + 1], acc[0][b]);
            acc[1][b] = ffma2(vx, w1[2 * c],     acc[1][b]);
            acc[1][b] = ffma2(vy, w1[2 * c + 1], acc[1][b]);
        }
    }
}

__global__ void __launch_bounds__(512, 1)
lstm_fused_kernel(const float* __restrict__ x,
                  const float* __restrict__ Wih0, const float* __restrict__ Whh0,
                  const float* __restrict__ bih0, const float* __restrict__ bhh0,
                  const float* __restrict__ Wih1, const float* __restrict__ Whh1,
                  const float* __restrict__ bih1, const float* __restrict__ bhh1,
                  const float* __restrict__ Wc1,  const float* __restrict__ bc1,
                  const float* __restrict__ Wc2,  const float* __restrict__ bc2,
                  float* __restrict__ out) {
    extern __shared__ char smem_raw[];
    Smem& s = *reinterpret_cast<Smem*>(smem_raw);
    const int tid  = threadIdx.x;
    const int half = tid >> 8;
    const int lt   = tid & 255;
    const int grp  = lt >> 7;          // group within half
    const int gg   = lt & 127;         // thread within group
    const int kh   = gg >> 6;          // k-half
    const int rl   = gg & 63;          // row (owns rl and rl+64)
    const bool is_l0 = ((grp ^ half) == 0);   // SMSP-balanced layer map
    const int bbase = blockIdx.x * BPB + half * NBH;

    // ---- zero state (xs, h0, h1 contiguous at struct start) ----
    {
        float* zp = reinterpret_cast<float*>(&s);
        const int zn = (int)((sizeof(s.xs) + sizeof(s.h0) + sizeof(s.h1)) / 4);
        for (int i = tid; i < zn; i += 512) zp[i] = 0.0f;
    }
    // ---- stage x(0) (batch-clamped for tail blocks) ----
    for (int i = tid; i < 2 * NBH * II; i += 512) {
        int hf = i / (NBH * II), r = i % (NBH * II), b = r / II, k = r % II;
        int gb = blockIdx.x * BPB + hf * NBH + b;
        if (gb > BB - 1) gb = BB - 1;
        s.xs[hf][0][b][k] = x[(size_t)gb * TT * II + k];
    }

    // ---- register-resident weights: rows (rl, rl+64), k-half kh ----
    ull wA[2][8], wB[2][8];
    ull biasA, biasB;
    if (is_l0) {
#pragma unroll
        for (int i = 0; i < 2; i++) {
            int r = rl + i * 64;
#pragma unroll
            for (int p = 0; p < 4; p++) {   // xs slice: pairs kh*4+p (k=2*(kh*4+p))
                int k = (kh * 4 + p) * 2;
                float lo = (k     < II) ? Wih0[r * II + k]     : 0.0f;
                float hi = (k + 1 < II) ? Wih0[r * II + k + 1] : 0.0f;
                wA[i][p] = packf2(lo, hi);
            }
#pragma unroll
            for (int p = 0; p < 8; p++) {   // h slice: pairs kh*8+p
                int k = (kh * 8 + p) * 2;
                wB[i][p] = packf2(Whh0[r * HH + k], Whh0[r * HH + k + 1]);
            }
        }
        biasA = (kh == 0) ? packf2(bih0[rl] + bhh0[rl], 0.0f) : 0ull;
        biasB = (kh == 0) ? packf2(bih0[rl + 64] + bhh0[rl + 64], 0.0f) : 0ull;
    } else {
#pragma unroll
        for (int i = 0; i < 2; i++) {
            int r = rl + i * 64;
#pragma unroll
            for (int p = 0; p < 8; p++) {
                int k = (kh * 8 + p) * 2;
                wA[i][p] = packf2(Wih1[r * HH + k], Wih1[r * HH + k + 1]);
                wB[i][p] = packf2(Whh1[r * HH + k], Whh1[r * HH + k + 1]);
            }
        }
        biasA = (kh == 0) ? packf2(bih1[rl] + bhh1[rl], 0.0f) : 0ull;
        biasB = (kh == 0) ? packf2(bih1[rl + 64] + bhh1[rl + 64], 0.0f) : 0ull;
    }

    // ---- EW map: unit u, batches (be, be+1); c-state in regs ----
    const int u  = gg & 31;
    const int be = (gg >> 5) * 2;      // 0,2,4,6
    float cst[2] = {0.f, 0.f};

    float* pgs = &s.pg[half][grp][kh][0];      // this thread's partial slice
    float* g0  = &s.pg[half][grp][0][0];       // group's partials (kh=0 base)

    // ---- x staging: one slot per L0 thread ----
    const int pb = gg >> 4, pk = gg & 15;
    const bool pv = (pb < NBH) && (pk < II);
    int cbb = bbase + pb; if (cbb > BB - 1) cbb = BB - 1;
    const float* xcp = x + (size_t)cbb * TT * II + pk;

    // barrier ids: idA[slot]=1+4h+slot, idB[slot]=3+4h+slot, GBAR=9+2h+grp
    const int idA0 = 1 + 4 * half;
    const int idB0 = 3 + 4 * half;
    const int idG  = 9 + 2 * half + grp;

    __syncthreads();

#define ARRV(id) asm volatile("bar.arrive %0, 256;" :: "r"(id) : "memory")
#define WAIT(id) asm volatile("bar.sync %0, 256;"   :: "r"(id) : "memory")
#define GBAR()   asm volatile("bar.sync %0, 128;"   :: "r"(idG) : "memory")

    for (int t = 0; t <= TT; t++) {
        const int par = t & 1;
        if (is_l0) {
            if (t < TT) {
                GBAR();   // intra-L0: h0(t-1) slot par / xs(t) visible
                float xn = 0.f;
                if (pv && (t + 1 < TT)) xn = xcp[(size_t)(t + 1) * II];
                // GEMM0 (k-slice): b0 + Wx0*x(t) + Wh0*h0(t-1)
                const float* xsv = &s.xs[half][par][0][0] + kh * 8;
                const float* h0v = &s.h0[half][par][0][0] + kh * 16;
                ull acc[2][NBH];
#pragma unroll
                for (int b = 0; b < NBH; b++) { acc[0][b] = biasA; acc[1][b] = biasB; }
                gemm2<2, 16>(acc, xsv, wA[0], wA[1]);
                gemm2<4, HH>(acc, h0v, wB[0], wB[1]);
#pragma unroll
                for (int b = 0; b < NBH; b++) {
                    pgs[rl * GSTR + b]        = hadd2(acc[0][b]);
                    pgs[(rl + 64) * GSTR + b] = hadd2(acc[1][b]);
                }
                GBAR();                              // partials visible
                if (t >= 2) WAIT(idB0 + (par ^ 1));  // L1 done with slot par^1
                // EW layer0 -> h0(t) in slot par^1 (sums the 2 k-partials)
#pragma unroll
                for (int j = 0; j < 2; j++) {
                    int b = be + j;
                    if (b < NBH) {
                        float gi = g0[u * GSTR + b]         + g0[KH1 + u * GSTR + b];
                        float gf = g0[(u + 32) * GSTR + b]  + g0[KH1 + (u + 32) * GSTR + b];
                        float gg_ = g0[(u + 64) * GSTR + b] + g0[KH1 + (u + 64) * GSTR + b];
                        float go = g0[(u + 96) * GSTR + b]  + g0[KH1 + (u + 96) * GSTR + b];
                        float ig = sigf(gi), fg = sigf(gf);
                        float gv = tanhap(gg_), og = sigf(go);
                        cst[j] = fmaf(fg, cst[j], ig * gv);
                        s.h0[half][par ^ 1][b][u] = og * tanhap(cst[j]);
                    }
                }
                ARRV(idA0 + (par ^ 1));              // h0(t) published
                if (pv && (t + 1 < TT)) s.xs[half][par ^ 1][pb][pk] = xn;
            }
        } else {
            if (t > 0) {
                // private part first: b1 + Whh1*h1(t-2) (k-slice)
                const float* h1v = &s.h1[half][0][0] + kh * 16;
                ull acc[2][NBH];
#pragma unroll
                for (int b = 0; b < NBH; b++) { acc[0][b] = biasA; acc[1][b] = biasB; }
                gemm2<4, HH>(acc, h1v, wB[0], wB[1]);
                WAIT(idA0 + par);                    // h0(t-1) ready in slot par
                const float* h0v = &s.h0[half][par][0][0] + kh * 16;
                gemm2<4, HH>(acc, h0v, wA[0], wA[1]);
#pragma unroll
                for (int b = 0; b < NBH; b++) {
                    pgs[rl * GSTR + b]        = hadd2(acc[0][b]);
                    pgs[(rl + 64) * GSTR + b] = hadd2(acc[1][b]);
                }
                ARRV(idB0 + par);                    // slot par consumed
                GBAR();                              // partials visible
                // EW layer1 -> h1(t-1)
#pragma unroll
                for (int j = 0; j < 2; j++) {
                    int b = be + j;
                    if (b < NBH) {
                        float gi = g0[u * GSTR + b]         + g0[KH1 + u * GSTR + b];
                        float gf = g0[(u + 32) * GSTR + b]  + g0[KH1 + (u + 32) * GSTR + b];
                        float gg_ = g0[(u + 64) * GSTR + b] + g0[KH1 + (u + 64) * GSTR + b];
                        float go = g0[(u + 96) * GSTR + b]  + g0[KH1 + (u + 96) * GSTR + b];
                        float ig = sigf(gi), fg = sigf(gf);
                        float gv = tanhap(gg_), og = sigf(go);
                        cst[j] = fmaf(fg, cst[j], ig * gv);
                        s.h1[half][b][u] = og * tanhap(cst[j]);
                    }
                }
                GBAR();                              // h1 visible in-group
            }
        }
    }
    __syncthreads();

    // ---- classifier head ----
    {
        int hj = lt & 31, hb = lt >> 5;    // hb 0..7
        float* hs = &s.pg[half][0][0][0];
        if (hb < NBH) {
            float a = bc1[hj];
#pragma unroll
            for (int k = 0; k < HH; k++)
                a = fmaf(s.h1[half][hb][k], Wc1[hj * HH + k], a);
            hs[hj * GSTR + hb] = fmaxf(a, 0.0f);
        }
    }
    __syncthreads();
    if (lt < NBH * NC) {
        int b = lt / NC, c = lt - b * NC;
        if (bbase + b < BB) {
            float* hs = &s.pg[half][0][0][0];
            float o = bc2[c];
#pragma unroll
            for (int j = 0; j < HH; j++)
                o = fmaf(hs[j * GSTR + b], Wc2[c * HH + j], o);
            out[(size_t)(bbase + b) * NC + c] = o;
        }
    }
#undef ARRV
#undef WAIT
#undef GBAR
}

extern "C" void kernel_launch(void* const* d_in, const int* in_sizes, int n_in,
                              void* d_out, int out_size) {
    const float* x    = (const float*)d_in[0];
    const float* Wih0 = (const float*)d_in[1];
    const float* Whh0 = (const float*)d_in[2];
    const float* bih0 = (const float*)d_in[3];
    const float* bhh0 = (const float*)d_in[4];
    const float* Wih1 = (const float*)d_in[5];
    const float* Whh1 = (const float*)d_in[6];
    const float* bih1 = (const float*)d_in[7];
    const float* bhh1 = (const float*)d_in[8];
    const float* Wc1  = (const float*)d_in[9];
    const float* bc1  = (const float*)d_in[10];
    const float* Wc2  = (const float*)d_in[11];
    const float* bc2  = (const float*)d_in[12];
    float* out = (float*)d_out;

    cudaFuncSetAttribute(lstm_fused_kernel,
                         cudaFuncAttributeMaxDynamicSharedMemorySize,
                         (int)sizeof(Smem));

    lstm_fused_kernel<<<GRIDN, 512, sizeof(Smem)>>>(
        x, Wih0, Whh0, bih0, bhh0, Wih1, Whh1, bih1, bhh1,
        Wc1, bc1, Wc2, bc2, out);
}